// round 15
// baseline (speedup 1.0000x reference)
#include <cuda_runtime.h>
#include <cuda_bf16.h>
#include <cuda_fp16.h>
#include <math.h>

#define NN   50000
#define NN2  50048           // padded to 128-row multiple
#define EE   800000
#define ET   850000          // EE + NN self loops
#define FIN  256
#define HID  64
#define HEADS 4
#define HF   256             // HEADS*HID
#define CLS  32
#define NEG  0.2f
#define DET_N 65536          // sampled edges for dtype detection
#define SCAN_B 49            // ceil(NN / 1024)

#define CP_ASYNC16(dst, src) \
    asm volatile("cp.async.cg.shared.global [%0], [%1], 16;" :: "r"(dst), "l"(src))
#define CP_COMMIT() asm volatile("cp.async.commit_group;")
#define CP_WAIT0()  asm volatile("cp.async.wait_group 0;")

// ---------------- scratch (static device arrays; no cudaMalloc) --------------
__device__ __align__(16) float    g_h1[NN * HF];     // x @ W1 (fp32, for att1)
__device__ __align__(16) __half   g_h1h[NN * HF];    // fp16 shadow for gathers
__device__ __align__(16) float    g_h2[NN * CLS];    // layer2 pre-softmax feats
__device__ __align__(16) float    g_als1[NN * HEADS];
__device__ __align__(16) float    g_ald1[NN * HEADS];
__device__ __align__(16) float    g_ex1[ET * HEADS]; // stored at CSR position
__device__ float    g_als2[NN];
__device__ float    g_ald2[NN];
__device__ int      g_deg[NN];
__device__ int      g_rowptr[NN + 1];
__device__ int      g_cursor[NN];
__device__ int      g_csr_src[ET];
__device__ int      g_bsum[SCAN_B];
__device__ int      g_boff[SCAN_B];
__device__ __align__(8) int2 g_edge[ET];              // (src, dst)
__device__ unsigned g_odd_or;
// bf16 split W1 for tensor-core GEMM1 (A converted in-kernel)
__device__ __align__(16) __nv_bfloat16 g_whi[FIN * HF];
__device__ __align__(16) __nv_bfloat16 g_wlo[FIN * HF];

__device__ __forceinline__ float lrelu(float v) { return v > 0.f ? v : NEG * v; }

// ---------------- init ----------------
__global__ void k_init() {
    int i = blockIdx.x * blockDim.x + threadIdx.x;
    int stride = gridDim.x * blockDim.x;
    if (i == 0) g_odd_or = 0u;
    for (int j = i; j < NN; j += stride) g_deg[j] = 0;
}

// ---------------- bf16 hi/lo conversion for W1 -------------------------------
__global__ void k_cvtW(const float* __restrict__ w) {
    int i = blockIdx.x * blockDim.x + threadIdx.x;
    if (i >= FIN * HF) return;
    float v = w[i];
    __nv_bfloat16 hi = __float2bfloat16_rn(v);
    g_whi[i] = hi;
    g_wlo[i] = __float2bfloat16_rn(v - __bfloat162float(hi));
}

// ------- detect int64 vs int32 edge_index (sampled: first DET_N edges) -------
__global__ void k_detect(const unsigned* __restrict__ w) {
    unsigned acc = 0;
    int stride = gridDim.x * blockDim.x;
    for (int i = blockIdx.x * blockDim.x + threadIdx.x; i < DET_N; i += stride)
        acc |= w[2 * i + 1];
#pragma unroll
    for (int o = 16; o; o >>= 1) acc |= __shfl_xor_sync(0xffffffffu, acc, o);
    __shared__ unsigned sacc[32];
    int lane = threadIdx.x & 31, wid = threadIdx.x >> 5;
    if (!lane) sacc[wid] = acc;
    __syncthreads();
    if (threadIdx.x == 0) {
        unsigned t = 0;
        for (int k = 0; k < (int)(blockDim.x >> 5); k++) t |= sacc[k];
        if (t) atomicOr(&g_odd_or, 1u);
    }
}

// decode edges (+ self loops) and count in-degree
__global__ void k_decode(const unsigned* __restrict__ w) {
    int e = blockIdx.x * blockDim.x + threadIdx.x;
    if (e >= ET) return;
    int s, d;
    if (e >= EE) { s = d = e - EE; }
    else if (g_odd_or == 0u) {   // int64 layout
        s = (int)w[2 * e];
        d = (int)w[2 * (EE + e)];
    } else {                     // int32 layout
        s = (int)w[e];
        d = (int)w[EE + e];
    }
    g_edge[e] = make_int2(s, d);
    atomicAdd(&g_deg[d], 1);
}

// ---------------- parallel 3-phase scan of degrees ---------------------------
__global__ void k_scanA() {
    __shared__ int wsum[32];
    int i = blockIdx.x * 1024 + threadIdx.x;
    int lane = threadIdx.x & 31, wid = threadIdx.x >> 5;
    int v = (i < NN) ? g_deg[i] : 0;
#pragma unroll
    for (int o = 1; o < 32; o <<= 1) {
        int u = __shfl_up_sync(0xffffffffu, v, o);
        if (lane >= o) v += u;
    }
    if (lane == 31) wsum[wid] = v;
    __syncthreads();
    if (wid == 0) {
        int wv = wsum[lane];
#pragma unroll
        for (int o = 1; o < 32; o <<= 1) {
            int u = __shfl_up_sync(0xffffffffu, wv, o);
            if (lane >= o) wv += u;
        }
        wsum[lane] = wv;
    }
    __syncthreads();
    int incl = v + (wid ? wsum[wid - 1] : 0);
    if (i < NN) g_rowptr[i + 1] = incl;
    if (threadIdx.x == 1023) g_bsum[blockIdx.x] = incl;
}

__global__ void k_scanB() {
    int lane = threadIdx.x;
    int v1 = (lane < SCAN_B) ? g_bsum[lane] : 0;
    int s1 = v1;
#pragma unroll
    for (int o = 1; o < 32; o <<= 1) {
        int u = __shfl_up_sync(0xffffffffu, s1, o);
        if (lane >= o) s1 += u;
    }
    int tot1 = __shfl_sync(0xffffffffu, s1, 31);
    if (lane < SCAN_B) g_boff[lane] = s1 - v1;
    int idx2 = 32 + lane;
    int v2 = (idx2 < SCAN_B) ? g_bsum[idx2] : 0;
    int s2 = v2;
#pragma unroll
    for (int o = 1; o < 32; o <<= 1) {
        int u = __shfl_up_sync(0xffffffffu, s2, o);
        if (lane >= o) s2 += u;
    }
    if (idx2 < SCAN_B) g_boff[idx2] = tot1 + s2 - v2;
}

__global__ void k_scanC() {
    int i = blockIdx.x * 1024 + threadIdx.x;
    if (i == 0) g_rowptr[0] = 0;
    if (i >= NN) return;
    int r = g_rowptr[i + 1] + g_boff[blockIdx.x];
    g_rowptr[i + 1] = r;
    g_cursor[i] = r - g_deg[i];
}

// ---------------- tensor-core GEMM1 (bf16x3 split, mma.sync) -----------------
#define SA_STRIDE 24   // bf16 elems per A smem row (16 data + 8 pad) = 48B
#define SB_STRIDE 136  // bf16 elems per B smem row (128 data + 8 pad) = 272B

__device__ __forceinline__ void mma_bf16(float* c, const unsigned* a, const unsigned* b) {
    asm volatile(
        "mma.sync.aligned.m16n8k16.row.col.f32.bf16.bf16.f32 "
        "{%0,%1,%2,%3},{%4,%5,%6,%7},{%8,%9},{%0,%1,%2,%3};"
        : "+f"(c[0]), "+f"(c[1]), "+f"(c[2]), "+f"(c[3])
        : "r"(a[0]), "r"(a[1]), "r"(a[2]), "r"(a[3]), "r"(b[0]), "r"(b[1]));
}
__device__ __forceinline__ void ldm_x4(unsigned* r, unsigned addr) {
    asm volatile("ldmatrix.sync.aligned.m8n8.x4.shared.b16 {%0,%1,%2,%3}, [%4];"
                 : "=r"(r[0]), "=r"(r[1]), "=r"(r[2]), "=r"(r[3]) : "r"(addr));
}
__device__ __forceinline__ void ldm_x2t(unsigned* r, unsigned addr) {
    asm volatile("ldmatrix.sync.aligned.m8n8.x2.trans.shared.b16 {%0,%1}, [%2];"
                 : "=r"(r[0]), "=r"(r[1]) : "r"(addr));
}

__global__ void __launch_bounds__(256) k_gemm1(const float* __restrict__ X) {
    __shared__ __nv_bfloat16 sA[2][2][128 * SA_STRIDE];  // [stage][hi/lo]
    __shared__ __nv_bfloat16 sB[2][2][16 * SB_STRIDE];
    int tid = threadIdx.x;
    int lane = tid & 31, wid = tid >> 5;
    int warp_m = wid >> 2, warp_n = wid & 3;     // 2 x 4 warps
    int rowBase = blockIdx.y * 128, colBase = blockIdx.x * 128;

    int aRow = tid >> 1;               // 0..127
    int aOff = (tid & 1) * 8;          // elem idx 0 or 8
    int bRow = tid >> 4;               // 0..15
    int bOff = (tid & 15) * 8;         // 0..120

    bool aValid = (rowBase + aRow) < NN;
    const float* aSrc = X + (rowBase + aRow) * FIN + aOff;
    const __nv_bfloat16* bHiSrc = g_whi + bRow * HF + colBase + bOff;
    const __nv_bfloat16* bLoSrc = g_wlo + bRow * HF + colBase + bOff;

    __nv_bfloat16* aHiDst[2];
    __nv_bfloat16* aLoDst[2];
    unsigned bHiDst[2], bLoDst[2];
#pragma unroll
    for (int s = 0; s < 2; s++) {
        aHiDst[s] = &sA[s][0][aRow * SA_STRIDE + aOff];
        aLoDst[s] = &sA[s][1][aRow * SA_STRIDE + aOff];
        bHiDst[s] = (unsigned)__cvta_generic_to_shared(&sB[s][0][bRow * SB_STRIDE + bOff]);
        bLoDst[s] = (unsigned)__cvta_generic_to_shared(&sB[s][1][bRow * SB_STRIDE + bOff]);
    }

    float C[4][4][4] = {};           // [mi][ni][reg]
    unsigned Ahi[4][4], Alo[4][4], Bhi[4][2], Blo[4][2];

    int lrow = lane & 15;
    int lcol = (lane >> 4) * 8;
    unsigned aAddrBase[2][2], bAddrBase[2][2];
#pragma unroll
    for (int s = 0; s < 2; s++)
#pragma unroll
        for (int hl = 0; hl < 2; hl++) {
            aAddrBase[s][hl] = (unsigned)__cvta_generic_to_shared(
                &sA[s][hl][(warp_m * 64 + lrow) * SA_STRIDE + lcol]);
            bAddrBase[s][hl] = (unsigned)__cvta_generic_to_shared(
                &sB[s][hl][lrow * SB_STRIDE + warp_n * 32]);
        }

    float va[8];
    auto cvtStore = [&](int s) {
#pragma unroll
        for (int i = 0; i < 8; i++) {
            __nv_bfloat16 hi = __float2bfloat16_rn(va[i]);
            aHiDst[s][i] = hi;
            aLoDst[s][i] = __float2bfloat16_rn(va[i] - __bfloat162float(hi));
        }
    };
    auto ldA = [&](int k0) {
        if (aValid) {
            float4 t0 = ((const float4*)(aSrc + k0))[0];
            float4 t1 = ((const float4*)(aSrc + k0))[1];
            va[0]=t0.x; va[1]=t0.y; va[2]=t0.z; va[3]=t0.w;
            va[4]=t1.x; va[5]=t1.y; va[6]=t1.z; va[7]=t1.w;
        } else {
#pragma unroll
            for (int i = 0; i < 8; i++) va[i] = 0.f;
        }
    };

    const int NIT = FIN / 16;        // 16 stages
    ldA(0);
    CP_ASYNC16(bHiDst[0], bHiSrc);
    CP_ASYNC16(bLoDst[0], bLoSrc);
    CP_COMMIT();
    cvtStore(0);
    CP_WAIT0();
    __syncthreads();

    for (int it = 0; it < NIT; it++) {
        int cur = it & 1;
        bool hasNext = (it + 1) < NIT;
        if (hasNext) {
            int k0 = (it + 1) * 16;
            ldA(k0);
            CP_ASYNC16(bHiDst[cur ^ 1], bHiSrc + k0 * HF);
            CP_ASYNC16(bLoDst[cur ^ 1], bLoSrc + k0 * HF);
            CP_COMMIT();
        }
#pragma unroll
        for (int mi = 0; mi < 4; mi++) {
            ldm_x4(Ahi[mi], aAddrBase[cur][0] + mi * 16 * SA_STRIDE * 2);
            ldm_x4(Alo[mi], aAddrBase[cur][1] + mi * 16 * SA_STRIDE * 2);
        }
#pragma unroll
        for (int ni = 0; ni < 4; ni++) {
            ldm_x2t(Bhi[ni], bAddrBase[cur][0] + ni * 16);
            ldm_x2t(Blo[ni], bAddrBase[cur][1] + ni * 16);
        }
#pragma unroll
        for (int mi = 0; mi < 4; mi++)
#pragma unroll
            for (int ni = 0; ni < 4; ni++) {
                mma_bf16(C[mi][ni], Ahi[mi], Bhi[ni]);
                mma_bf16(C[mi][ni], Ahi[mi], Blo[ni]);
                mma_bf16(C[mi][ni], Alo[mi], Bhi[ni]);
            }
        if (hasNext) {
            cvtStore(cur ^ 1);
            CP_WAIT0();
        }
        __syncthreads();
    }
    // epilogue: fp32 h1 + fp16 shadow for the aggregation gather
    int gtr = lane >> 2, gtc = (lane & 3) * 2;
#pragma unroll
    for (int mi = 0; mi < 4; mi++) {
        int r0 = rowBase + warp_m * 64 + mi * 16 + gtr;
#pragma unroll
        for (int ni = 0; ni < 4; ni++) {
            int c0 = colBase + warp_n * 32 + ni * 8 + gtc;
            if (r0 < NN) {
                *(float2*)(g_h1 + r0 * HF + c0) = make_float2(C[mi][ni][0], C[mi][ni][1]);
                *(__half2*)(g_h1h + r0 * HF + c0) = __floats2half2_rn(C[mi][ni][0], C[mi][ni][1]);
            }
            if (r0 + 8 < NN) {
                *(float2*)(g_h1 + (r0 + 8) * HF + c0) = make_float2(C[mi][ni][2], C[mi][ni][3]);
                *(__half2*)(g_h1h + (r0 + 8) * HF + c0) = __floats2half2_rn(C[mi][ni][2], C[mi][ni][3]);
            }
        }
    }
}

// ---------------- attention logits layer1: warp per (node, head) -------------
__global__ void k_att1(const float* __restrict__ a_src, const float* __restrict__ a_dst) {
    int w = (blockIdx.x * blockDim.x + threadIdx.x) >> 5;
    int lane = threadIdx.x & 31;
    if (w >= NN * HEADS) return;
    int n = w >> 2, h = w & 3;
    const float* hr = g_h1 + n * HF + h * HID;
    const float* as = a_src + h * HID;
    const float* ad = a_dst + h * HID;
    float v0 = hr[lane], v1 = hr[lane + 32];
    float s = v0 * as[lane] + v1 * as[lane + 32];
    float d = v0 * ad[lane] + v1 * ad[lane + 32];
#pragma unroll
    for (int o = 16; o; o >>= 1) {
        s += __shfl_xor_sync(0xffffffffu, s, o);
        d += __shfl_xor_sync(0xffffffffu, d, o);
    }
    if (!lane) { g_als1[n * HEADS + h] = s; g_ald1[n * HEADS + h] = d; }
}

// ---------------- edge pass 1: exp (no max shift) + CSR scatter --------------
__global__ void k_edge_exp1() {
    int e = blockIdx.x * blockDim.x + threadIdx.x;
    if (e >= ET) return;
    int2 ed = g_edge[e];
    int pos = atomicAdd(&g_cursor[ed.y], 1);
    g_csr_src[pos] = ed.x;
    float4 as = ((const float4*)g_als1)[ed.x];
    float4 ad = ((const float4*)g_ald1)[ed.y];
    float e0 = __expf(lrelu(as.x + ad.x));
    float e1 = __expf(lrelu(as.y + ad.y));
    float e2 = __expf(lrelu(as.z + ad.z));
    float e3 = __expf(lrelu(as.w + ad.w));
    ((float4*)g_ex1)[pos] = make_float4(e0, e1, e2, e3);
}

// ------- fused: aggregate layer1 (fp16 gather) + bias + elu + GEMM2 + att2 ---
__global__ void __launch_bounds__(256) k_fused1(const float* __restrict__ b1,
                                                const float* __restrict__ W2,
                                                const float* __restrict__ a_src2,
                                                const float* __restrict__ a_dst2) {
    __shared__ float sW[FIN * CLS];       // 32 KB
    __shared__ float sv[8][FIN];          // 8 KB
    int tid = threadIdx.x;
    for (int i = tid; i < FIN * CLS; i += 256) sW[i] = W2[i];

    int h = tid >> 6;
    float bb = b1[tid];
#pragma unroll 1
    for (int i = 0; i < 8; i++) {
        int n = blockIdx.x * 8 + i;
        int beg = g_rowptr[n], end = g_rowptr[n + 1];
        float acc0 = 0.f, acc1 = 0.f, den0 = 0.f, den1 = 0.f;
        int k = beg;
        for (; k + 2 <= end; k += 2) {
            int s0 = g_csr_src[k], s1 = g_csr_src[k + 1];
            float e0 = g_ex1[k * HEADS + h];
            float e1 = g_ex1[(k + 1) * HEADS + h];
            acc0 += e0 * __half2float(g_h1h[s0 * HF + tid]);
            acc1 += e1 * __half2float(g_h1h[s1 * HF + tid]);
            den0 += e0; den1 += e1;
        }
        if (k < end) {
            int s0 = g_csr_src[k];
            float e0 = g_ex1[k * HEADS + h];
            acc0 += e0 * __half2float(g_h1h[s0 * HF + tid]);
            den0 += e0;
        }
        float v = (acc0 + acc1) * __fdividef(1.f, den0 + den1) + bb;
        sv[i][tid] = v > 0.f ? v : expm1f(v);
    }
    __syncthreads();

    int lane = tid & 31, w = tid >> 5;
    int n = blockIdx.x * 8 + w;
    float xv[8];
#pragma unroll
    for (int j = 0; j < 8; j++) xv[j] = sv[w][j * 32 + lane];
    float acc = 0.f;
#pragma unroll
    for (int j = 0; j < 8; j++)
#pragma unroll
        for (int t = 0; t < 32; t++)
            acc += __shfl_sync(0xffffffffu, xv[j], t) * sW[(j * 32 + t) * CLS + lane];
    g_h2[n * CLS + lane] = acc;
    float s = acc * a_src2[lane], d = acc * a_dst2[lane];
#pragma unroll
    for (int o = 16; o; o >>= 1) {
        s += __shfl_xor_sync(0xffffffffu, s, o);
        d += __shfl_xor_sync(0xffffffffu, d, o);
    }
    if (!lane) { g_als2[n] = s; g_ald2[n] = d; }
}

// ------- aggregate layer2: lane-parallel exp + bias + fused log_softmax ------
__global__ void k_agg2(const float* __restrict__ b2, float* __restrict__ out) {
    int w = (blockIdx.x * blockDim.x + threadIdx.x) >> 5;
    int lane = threadIdx.x & 31;
    if (w >= NN) return;
    int beg = g_rowptr[w], end = g_rowptr[w + 1];
    float ald = g_ald2[w];
    float acc = 0.f, den = 0.f;
    for (int k = beg; k < end; k += 32) {
        int cnt = min(32, end - k);
        int mysrc = 0;
        float myex = 0.f;
        if (lane < cnt) {
            mysrc = g_csr_src[k + lane];
            myex = __expf(lrelu(g_als2[mysrc] + ald));
        }
        den += myex;
        for (int t = 0; t < cnt; t++) {
            float ex = __shfl_sync(0xffffffffu, myex, t);
            int s = __shfl_sync(0xffffffffu, mysrc, t);
            acc += ex * g_h2[s * CLS + lane];
        }
    }
#pragma unroll
    for (int o = 16; o; o >>= 1) den += __shfl_xor_sync(0xffffffffu, den, o);
    float v = acc * __fdividef(1.f, den) + b2[lane];
    float m = v;
#pragma unroll
    for (int o = 16; o; o >>= 1) m = fmaxf(m, __shfl_xor_sync(0xffffffffu, m, o));
    float ex = __expf(v - m);
    float sum = ex;
#pragma unroll
    for (int o = 16; o; o >>= 1) sum += __shfl_xor_sync(0xffffffffu, sum, o);
    out[w * CLS + lane] = v - m - logf(sum);
}

// -----------------------------------------------------------------------------
extern "C" void kernel_launch(void* const* d_in, const int* in_sizes, int n_in,
                              void* d_out, int out_size) {
    const float*    x      = (const float*)d_in[0];
    const unsigned* ei     = (const unsigned*)d_in[1];
    const float*    W1     = (const float*)d_in[2];
    const float*    a_src1 = (const float*)d_in[3];
    const float*    a_dst1 = (const float*)d_in[4];
    const float*    b1     = (const float*)d_in[5];
    const float*    W2     = (const float*)d_in[6];
    const float*    a_src2 = (const float*)d_in[7];
    const float*    a_dst2 = (const float*)d_in[8];
    const float*    b2     = (const float*)d_in[9];
    float*          out    = (float*)d_out;

    const int EB = (ET + 255) / 256;           // edge-parallel blocks

    cudaStream_t s2;
    cudaStreamCreate(&s2);
    cudaEvent_t evFork, evJoin;
    cudaEventCreateWithFlags(&evFork, cudaEventDisableTiming);
    cudaEventCreateWithFlags(&evJoin, cudaEventDisableTiming);

    // common init (deg=0, odd_or=0) on the main (capture) stream
    k_init<<<256, 256>>>();

    // fork: edge chain runs on s2 concurrently with the matrix chain
    cudaEventRecord(evFork, 0);
    cudaStreamWaitEvent(s2, evFork, 0);

    // edge chain (stream s2)
    k_detect<<<64, 256, 0, s2>>>(ei);
    k_decode<<<EB, 256, 0, s2>>>(ei);
    k_scanA<<<SCAN_B, 1024, 0, s2>>>();
    k_scanB<<<1, 32, 0, s2>>>();
    k_scanC<<<SCAN_B, 1024, 0, s2>>>();

    // matrix chain (main stream)
    k_cvtW<<<FIN * HF / 256, 256>>>(W1);
    k_gemm1<<<dim3(2, NN2 / 128), 256>>>(x);
    k_att1<<<(NN * HEADS * 32 + 255) / 256, 256>>>(a_src1, a_dst1);

    // join: edge_exp1 needs als1/ald1 (main) + cursor/rowptr (s2)
    cudaEventRecord(evJoin, s2);
    cudaStreamWaitEvent(0, evJoin, 0);

    k_edge_exp1<<<EB, 256>>>();
    k_fused1<<<NN / 8, 256>>>(b1, W2, a_src2, a_dst2);
    k_agg2<<<(NN * 32 + 255) / 256, 256>>>(b2, out);

    cudaEventDestroy(evFork);
    cudaEventDestroy(evJoin);
    cudaStreamDestroy(s2);
}

// round 16
// speedup vs baseline: 1.0256x; 1.0256x over previous
#include <cuda_runtime.h>
#include <cuda_bf16.h>
#include <math.h>

#define NN   50000
#define NN2  50048           // padded to 128-row multiple
#define EE   800000
#define ET   850000          // EE + NN self loops
#define FIN  256
#define HID  64
#define HEADS 4
#define HF   256             // HEADS*HID
#define CLS  32
#define NEG  0.2f
#define DET_N 65536          // sampled edges for dtype detection
#define SCAN_B 49            // ceil(NN / 1024)

#define CP_ASYNC16(dst, src) \
    asm volatile("cp.async.cg.shared.global [%0], [%1], 16;" :: "r"(dst), "l"(src))
#define CP_COMMIT() asm volatile("cp.async.commit_group;")
#define CP_WAIT0()  asm volatile("cp.async.wait_group 0;")

// ---------------- scratch (static device arrays; no cudaMalloc) --------------
__device__ __align__(16) float    g_h1[NN * HF];     // x @ W1
__device__ __align__(16) float    g_h2[NN * CLS];    // layer2 pre-softmax feats
__device__ __align__(16) float    g_als1[NN * HEADS];
__device__ __align__(16) float    g_ald1[NN * HEADS];
__device__ __align__(16) float    g_ex1[ET * HEADS]; // stored at CSR position
__device__ float    g_als2[NN];
__device__ float    g_ald2[NN];
__device__ int      g_deg[NN];
__device__ int      g_rowptr[NN + 1];
__device__ int      g_cursor[NN];
__device__ int      g_csr_src[ET];
__device__ int      g_pos[ET];                        // edge -> CSR position
__device__ int      g_bsum[SCAN_B];
__device__ int      g_boff[SCAN_B];
__device__ __align__(8) int2 g_edge[ET];              // (src, dst)
__device__ unsigned g_odd_or;
// bf16 split W1 for tensor-core GEMM1 (A converted in-kernel)
__device__ __align__(16) __nv_bfloat16 g_whi[FIN * HF];
__device__ __align__(16) __nv_bfloat16 g_wlo[FIN * HF];

__device__ __forceinline__ float lrelu(float v) { return v > 0.f ? v : NEG * v; }

// ---------------- init ----------------
__global__ void k_init() {
    int i = blockIdx.x * blockDim.x + threadIdx.x;
    int stride = gridDim.x * blockDim.x;
    if (i == 0) g_odd_or = 0u;
    for (int j = i; j < NN; j += stride) g_deg[j] = 0;
}

// ---------------- bf16 hi/lo conversion for W1 -------------------------------
__global__ void k_cvtW(const float* __restrict__ w) {
    int i = blockIdx.x * blockDim.x + threadIdx.x;
    if (i >= FIN * HF) return;
    float v = w[i];
    __nv_bfloat16 hi = __float2bfloat16_rn(v);
    g_whi[i] = hi;
    g_wlo[i] = __float2bfloat16_rn(v - __bfloat162float(hi));
}

// ------- detect int64 vs int32 edge_index (sampled: first DET_N edges) -------
__global__ void k_detect(const unsigned* __restrict__ w) {
    unsigned acc = 0;
    int stride = gridDim.x * blockDim.x;
    for (int i = blockIdx.x * blockDim.x + threadIdx.x; i < DET_N; i += stride)
        acc |= w[2 * i + 1];
#pragma unroll
    for (int o = 16; o; o >>= 1) acc |= __shfl_xor_sync(0xffffffffu, acc, o);
    __shared__ unsigned sacc[32];
    int lane = threadIdx.x & 31, wid = threadIdx.x >> 5;
    if (!lane) sacc[wid] = acc;
    __syncthreads();
    if (threadIdx.x == 0) {
        unsigned t = 0;
        for (int k = 0; k < (int)(blockDim.x >> 5); k++) t |= sacc[k];
        if (t) atomicOr(&g_odd_or, 1u);
    }
}

// decode edges (+ self loops) and count in-degree
__global__ void k_decode(const unsigned* __restrict__ w) {
    int e = blockIdx.x * blockDim.x + threadIdx.x;
    if (e >= ET) return;
    int s, d;
    if (e >= EE) { s = d = e - EE; }
    else if (g_odd_or == 0u) {   // int64 layout
        s = (int)w[2 * e];
        d = (int)w[2 * (EE + e)];
    } else {                     // int32 layout
        s = (int)w[e];
        d = (int)w[EE + e];
    }
    g_edge[e] = make_int2(s, d);
    atomicAdd(&g_deg[d], 1);
}

// ---------------- parallel 3-phase scan of degrees ---------------------------
__global__ void k_scanA() {
    __shared__ int wsum[32];
    int i = blockIdx.x * 1024 + threadIdx.x;
    int lane = threadIdx.x & 31, wid = threadIdx.x >> 5;
    int v = (i < NN) ? g_deg[i] : 0;
#pragma unroll
    for (int o = 1; o < 32; o <<= 1) {
        int u = __shfl_up_sync(0xffffffffu, v, o);
        if (lane >= o) v += u;
    }
    if (lane == 31) wsum[wid] = v;
    __syncthreads();
    if (wid == 0) {
        int wv = wsum[lane];
#pragma unroll
        for (int o = 1; o < 32; o <<= 1) {
            int u = __shfl_up_sync(0xffffffffu, wv, o);
            if (lane >= o) wv += u;
        }
        wsum[lane] = wv;
    }
    __syncthreads();
    int incl = v + (wid ? wsum[wid - 1] : 0);
    if (i < NN) g_rowptr[i + 1] = incl;
    if (threadIdx.x == 1023) g_bsum[blockIdx.x] = incl;
}

__global__ void k_scanB() {
    int lane = threadIdx.x;
    int v1 = (lane < SCAN_B) ? g_bsum[lane] : 0;
    int s1 = v1;
#pragma unroll
    for (int o = 1; o < 32; o <<= 1) {
        int u = __shfl_up_sync(0xffffffffu, s1, o);
        if (lane >= o) s1 += u;
    }
    int tot1 = __shfl_sync(0xffffffffu, s1, 31);
    if (lane < SCAN_B) g_boff[lane] = s1 - v1;
    int idx2 = 32 + lane;
    int v2 = (idx2 < SCAN_B) ? g_bsum[idx2] : 0;
    int s2 = v2;
#pragma unroll
    for (int o = 1; o < 32; o <<= 1) {
        int u = __shfl_up_sync(0xffffffffu, s2, o);
        if (lane >= o) s2 += u;
    }
    if (idx2 < SCAN_B) g_boff[idx2] = tot1 + s2 - v2;
}

__global__ void k_scanC() {
    int i = blockIdx.x * 1024 + threadIdx.x;
    if (i == 0) g_rowptr[0] = 0;
    if (i >= NN) return;
    int r = g_rowptr[i + 1] + g_boff[blockIdx.x];
    g_rowptr[i + 1] = r;
    g_cursor[i] = r - g_deg[i];
}

// ---------------- CSR scatter (edge chain only; hidden under GEMM1) ----------
__global__ void k_csr() {
    int e = blockIdx.x * blockDim.x + threadIdx.x;
    if (e >= ET) return;
    int2 ed = g_edge[e];
    int pos = atomicAdd(&g_cursor[ed.y], 1);
    g_csr_src[pos] = ed.x;
    g_pos[e] = pos;
}

// ---------------- tensor-core GEMM1 (bf16x3 split, mma.sync) -----------------
#define SA_STRIDE 24   // bf16 elems per A smem row (16 data + 8 pad) = 48B
#define SB_STRIDE 136  // bf16 elems per B smem row (128 data + 8 pad) = 272B

__device__ __forceinline__ void mma_bf16(float* c, const unsigned* a, const unsigned* b) {
    asm volatile(
        "mma.sync.aligned.m16n8k16.row.col.f32.bf16.bf16.f32 "
        "{%0,%1,%2,%3},{%4,%5,%6,%7},{%8,%9},{%0,%1,%2,%3};"
        : "+f"(c[0]), "+f"(c[1]), "+f"(c[2]), "+f"(c[3])
        : "r"(a[0]), "r"(a[1]), "r"(a[2]), "r"(a[3]), "r"(b[0]), "r"(b[1]));
}
__device__ __forceinline__ void ldm_x4(unsigned* r, unsigned addr) {
    asm volatile("ldmatrix.sync.aligned.m8n8.x4.shared.b16 {%0,%1,%2,%3}, [%4];"
                 : "=r"(r[0]), "=r"(r[1]), "=r"(r[2]), "=r"(r[3]) : "r"(addr));
}
__device__ __forceinline__ void ldm_x2t(unsigned* r, unsigned addr) {
    asm volatile("ldmatrix.sync.aligned.m8n8.x2.trans.shared.b16 {%0,%1}, [%2];"
                 : "=r"(r[0]), "=r"(r[1]) : "r"(addr));
}

__global__ void __launch_bounds__(256) k_gemm1(const float* __restrict__ X) {
    __shared__ __nv_bfloat16 sA[2][2][128 * SA_STRIDE];  // [stage][hi/lo]
    __shared__ __nv_bfloat16 sB[2][2][16 * SB_STRIDE];
    int tid = threadIdx.x;
    int lane = tid & 31, wid = tid >> 5;
    int warp_m = wid >> 2, warp_n = wid & 3;     // 2 x 4 warps
    int rowBase = blockIdx.y * 128, colBase = blockIdx.x * 128;

    int aRow = tid >> 1;               // 0..127
    int aOff = (tid & 1) * 8;          // elem idx 0 or 8
    int bRow = tid >> 4;               // 0..15
    int bOff = (tid & 15) * 8;         // 0..120

    bool aValid = (rowBase + aRow) < NN;
    const float* aSrc = X + (rowBase + aRow) * FIN + aOff;
    const __nv_bfloat16* bHiSrc = g_whi + bRow * HF + colBase + bOff;
    const __nv_bfloat16* bLoSrc = g_wlo + bRow * HF + colBase + bOff;

    __nv_bfloat16* aHiDst[2];
    __nv_bfloat16* aLoDst[2];
    unsigned bHiDst[2], bLoDst[2];
#pragma unroll
    for (int s = 0; s < 2; s++) {
        aHiDst[s] = &sA[s][0][aRow * SA_STRIDE + aOff];
        aLoDst[s] = &sA[s][1][aRow * SA_STRIDE + aOff];
        bHiDst[s] = (unsigned)__cvta_generic_to_shared(&sB[s][0][bRow * SB_STRIDE + bOff]);
        bLoDst[s] = (unsigned)__cvta_generic_to_shared(&sB[s][1][bRow * SB_STRIDE + bOff]);
    }

    float C[4][4][4] = {};           // [mi][ni][reg]
    unsigned Ahi[4][4], Alo[4][4], Bhi[4][2], Blo[4][2];

    int lrow = lane & 15;
    int lcol = (lane >> 4) * 8;
    unsigned aAddrBase[2][2], bAddrBase[2][2];
#pragma unroll
    for (int s = 0; s < 2; s++)
#pragma unroll
        for (int hl = 0; hl < 2; hl++) {
            aAddrBase[s][hl] = (unsigned)__cvta_generic_to_shared(
                &sA[s][hl][(warp_m * 64 + lrow) * SA_STRIDE + lcol]);
            bAddrBase[s][hl] = (unsigned)__cvta_generic_to_shared(
                &sB[s][hl][lrow * SB_STRIDE + warp_n * 32]);
        }

    float va[8];
    auto cvtStore = [&](int s) {
#pragma unroll
        for (int i = 0; i < 8; i++) {
            __nv_bfloat16 hi = __float2bfloat16_rn(va[i]);
            aHiDst[s][i] = hi;
            aLoDst[s][i] = __float2bfloat16_rn(va[i] - __bfloat162float(hi));
        }
    };
    auto ldA = [&](int k0) {
        if (aValid) {
            float4 t0 = ((const float4*)(aSrc + k0))[0];
            float4 t1 = ((const float4*)(aSrc + k0))[1];
            va[0]=t0.x; va[1]=t0.y; va[2]=t0.z; va[3]=t0.w;
            va[4]=t1.x; va[5]=t1.y; va[6]=t1.z; va[7]=t1.w;
        } else {
#pragma unroll
            for (int i = 0; i < 8; i++) va[i] = 0.f;
        }
    };

    const int NIT = FIN / 16;        // 16 stages
    ldA(0);
    CP_ASYNC16(bHiDst[0], bHiSrc);
    CP_ASYNC16(bLoDst[0], bLoSrc);
    CP_COMMIT();
    cvtStore(0);
    CP_WAIT0();
    __syncthreads();

    for (int it = 0; it < NIT; it++) {
        int cur = it & 1;
        bool hasNext = (it + 1) < NIT;
        if (hasNext) {
            int k0 = (it + 1) * 16;
            ldA(k0);
            CP_ASYNC16(bHiDst[cur ^ 1], bHiSrc + k0 * HF);
            CP_ASYNC16(bLoDst[cur ^ 1], bLoSrc + k0 * HF);
            CP_COMMIT();
        }
#pragma unroll
        for (int mi = 0; mi < 4; mi++) {
            ldm_x4(Ahi[mi], aAddrBase[cur][0] + mi * 16 * SA_STRIDE * 2);
            ldm_x4(Alo[mi], aAddrBase[cur][1] + mi * 16 * SA_STRIDE * 2);
        }
#pragma unroll
        for (int ni = 0; ni < 4; ni++) {
            ldm_x2t(Bhi[ni], bAddrBase[cur][0] + ni * 16);
            ldm_x2t(Blo[ni], bAddrBase[cur][1] + ni * 16);
        }
#pragma unroll
        for (int mi = 0; mi < 4; mi++)
#pragma unroll
            for (int ni = 0; ni < 4; ni++) {
                mma_bf16(C[mi][ni], Ahi[mi], Bhi[ni]);
                mma_bf16(C[mi][ni], Ahi[mi], Blo[ni]);
                mma_bf16(C[mi][ni], Alo[mi], Bhi[ni]);
            }
        if (hasNext) {
            cvtStore(cur ^ 1);
            CP_WAIT0();
        }
        __syncthreads();
    }
    // epilogue
    int gtr = lane >> 2, gtc = (lane & 3) * 2;
#pragma unroll
    for (int mi = 0; mi < 4; mi++) {
        int r0 = rowBase + warp_m * 64 + mi * 16 + gtr;
#pragma unroll
        for (int ni = 0; ni < 4; ni++) {
            int c0 = colBase + warp_n * 32 + ni * 8 + gtc;
            if (r0 < NN)
                *(float2*)(g_h1 + r0 * HF + c0) = make_float2(C[mi][ni][0], C[mi][ni][1]);
            if (r0 + 8 < NN)
                *(float2*)(g_h1 + (r0 + 8) * HF + c0) = make_float2(C[mi][ni][2], C[mi][ni][3]);
        }
    }
}

// ---------------- attention logits layer1: warp per (node, head) -------------
__global__ void k_att1(const float* __restrict__ a_src, const float* __restrict__ a_dst) {
    int w = (blockIdx.x * blockDim.x + threadIdx.x) >> 5;
    int lane = threadIdx.x & 31;
    if (w >= NN * HEADS) return;
    int n = w >> 2, h = w & 3;
    const float* hr = g_h1 + n * HF + h * HID;
    const float* as = a_src + h * HID;
    const float* ad = a_dst + h * HID;
    float v0 = hr[lane], v1 = hr[lane + 32];
    float s = v0 * as[lane] + v1 * as[lane + 32];
    float d = v0 * ad[lane] + v1 * ad[lane + 32];
#pragma unroll
    for (int o = 16; o; o >>= 1) {
        s += __shfl_xor_sync(0xffffffffu, s, o);
        d += __shfl_xor_sync(0xffffffffu, d, o);
    }
    if (!lane) { g_als1[n * HEADS + h] = s; g_ald1[n * HEADS + h] = d; }
}

// ---------------- edge pass: exp only (atomic-free; pos precomputed) ---------
__global__ void k_edge_exp1() {
    int e = blockIdx.x * blockDim.x + threadIdx.x;
    if (e >= ET) return;
    int2 ed = g_edge[e];
    int pos = g_pos[e];
    float4 as = ((const float4*)g_als1)[ed.x];
    float4 ad = ((const float4*)g_ald1)[ed.y];
    float e0 = __expf(lrelu(as.x + ad.x));
    float e1 = __expf(lrelu(as.y + ad.y));
    float e2 = __expf(lrelu(as.z + ad.z));
    float e3 = __expf(lrelu(as.w + ad.w));
    ((float4*)g_ex1)[pos] = make_float4(e0, e1, e2, e3);
}

// ------- fused: aggregate layer1 + bias + elu + GEMM2 + att2 logits ----------
__global__ void __launch_bounds__(256) k_fused1(const float* __restrict__ b1,
                                                const float* __restrict__ W2,
                                                const float* __restrict__ a_src2,
                                                const float* __restrict__ a_dst2) {
    __shared__ float sW[FIN * CLS];       // 32 KB
    __shared__ float sv[8][FIN];          // 8 KB
    int tid = threadIdx.x;
    for (int i = tid; i < FIN * CLS; i += 256) sW[i] = W2[i];

    int h = tid >> 6;
    float bb = b1[tid];
#pragma unroll 1
    for (int i = 0; i < 8; i++) {
        int n = blockIdx.x * 8 + i;
        int beg = g_rowptr[n], end = g_rowptr[n + 1];
        float acc0 = 0.f, acc1 = 0.f, den0 = 0.f, den1 = 0.f;
        int k = beg;
        for (; k + 2 <= end; k += 2) {
            int s0 = g_csr_src[k], s1 = g_csr_src[k + 1];
            float e0 = g_ex1[k * HEADS + h];
            float e1 = g_ex1[(k + 1) * HEADS + h];
            acc0 += e0 * g_h1[s0 * HF + tid];
            acc1 += e1 * g_h1[s1 * HF + tid];
            den0 += e0; den1 += e1;
        }
        if (k < end) {
            int s0 = g_csr_src[k];
            float e0 = g_ex1[k * HEADS + h];
            acc0 += e0 * g_h1[s0 * HF + tid];
            den0 += e0;
        }
        float v = (acc0 + acc1) * __fdividef(1.f, den0 + den1) + bb;
        sv[i][tid] = v > 0.f ? v : expm1f(v);
    }
    __syncthreads();

    int lane = tid & 31, w = tid >> 5;
    int n = blockIdx.x * 8 + w;
    float xv[8];
#pragma unroll
    for (int j = 0; j < 8; j++) xv[j] = sv[w][j * 32 + lane];
    float acc = 0.f;
#pragma unroll
    for (int j = 0; j < 8; j++)
#pragma unroll
        for (int t = 0; t < 32; t++)
            acc += __shfl_sync(0xffffffffu, xv[j], t) * sW[(j * 32 + t) * CLS + lane];
    g_h2[n * CLS + lane] = acc;
    float s = acc * a_src2[lane], d = acc * a_dst2[lane];
#pragma unroll
    for (int o = 16; o; o >>= 1) {
        s += __shfl_xor_sync(0xffffffffu, s, o);
        d += __shfl_xor_sync(0xffffffffu, d, o);
    }
    if (!lane) { g_als2[n] = s; g_ald2[n] = d; }
}

// ------- aggregate layer2: lane-parallel exp + bias + fused log_softmax ------
__global__ void k_agg2(const float* __restrict__ b2, float* __restrict__ out) {
    int w = (blockIdx.x * blockDim.x + threadIdx.x) >> 5;
    int lane = threadIdx.x & 31;
    if (w >= NN) return;
    int beg = g_rowptr[w], end = g_rowptr[w + 1];
    float ald = g_ald2[w];
    float acc = 0.f, den = 0.f;
    for (int k = beg; k < end; k += 32) {
        int cnt = min(32, end - k);
        int mysrc = 0;
        float myex = 0.f;
        if (lane < cnt) {
            mysrc = g_csr_src[k + lane];
            myex = __expf(lrelu(g_als2[mysrc] + ald));
        }
        den += myex;
        for (int t = 0; t < cnt; t++) {
            float ex = __shfl_sync(0xffffffffu, myex, t);
            int s = __shfl_sync(0xffffffffu, mysrc, t);
            acc += ex * g_h2[s * CLS + lane];
        }
    }
#pragma unroll
    for (int o = 16; o; o >>= 1) den += __shfl_xor_sync(0xffffffffu, den, o);
    float v = acc * __fdividef(1.f, den) + b2[lane];
    float m = v;
#pragma unroll
    for (int o = 16; o; o >>= 1) m = fmaxf(m, __shfl_xor_sync(0xffffffffu, m, o));
    float ex = __expf(v - m);
    float sum = ex;
#pragma unroll
    for (int o = 16; o; o >>= 1) sum += __shfl_xor_sync(0xffffffffu, sum, o);
    out[w * CLS + lane] = v - m - logf(sum);
}

// -----------------------------------------------------------------------------
extern "C" void kernel_launch(void* const* d_in, const int* in_sizes, int n_in,
                              void* d_out, int out_size) {
    const float*    x      = (const float*)d_in[0];
    const unsigned* ei     = (const unsigned*)d_in[1];
    const float*    W1     = (const float*)d_in[2];
    const float*    a_src1 = (const float*)d_in[3];
    const float*    a_dst1 = (const float*)d_in[4];
    const float*    b1     = (const float*)d_in[5];
    const float*    W2     = (const float*)d_in[6];
    const float*    a_src2 = (const float*)d_in[7];
    const float*    a_dst2 = (const float*)d_in[8];
    const float*    b2     = (const float*)d_in[9];
    float*          out    = (float*)d_out;

    const int EB = (ET + 255) / 256;           // edge-parallel blocks

    cudaStream_t s2;
    cudaStreamCreate(&s2);
    cudaEvent_t evFork, evJoin;
    cudaEventCreateWithFlags(&evFork, cudaEventDisableTiming);
    cudaEventCreateWithFlags(&evJoin, cudaEventDisableTiming);

    // common init (deg=0, odd_or=0) on the main (capture) stream
    k_init<<<256, 256>>>();

    // fork: edge chain runs on s2 concurrently with the matrix chain
    cudaEventRecord(evFork, 0);
    cudaStreamWaitEvent(s2, evFork, 0);

    // edge chain (stream s2): full CSR build incl. atomic scatter
    k_detect<<<64, 256, 0, s2>>>(ei);
    k_decode<<<EB, 256, 0, s2>>>(ei);
    k_scanA<<<SCAN_B, 1024, 0, s2>>>();
    k_scanB<<<1, 32, 0, s2>>>();
    k_scanC<<<SCAN_B, 1024, 0, s2>>>();
    k_csr<<<EB, 256, 0, s2>>>();

    // matrix chain (main stream)
    k_cvtW<<<FIN * HF / 256, 256>>>(W1);
    k_gemm1<<<dim3(2, NN2 / 128), 256>>>(x);
    k_att1<<<(NN * HEADS * 32 + 255) / 256, 256>>>(a_src1, a_dst1);

    // join: edge_exp1 needs als1/ald1 (main) + pos/csr (s2)
    cudaEventRecord(evJoin, s2);
    cudaStreamWaitEvent(0, evJoin, 0);

    k_edge_exp1<<<EB, 256>>>();
    k_fused1<<<NN / 8, 256>>>(b1, W2, a_src2, a_dst2);
    k_agg2<<<(NN * 32 + 255) / 256, 256>>>(b2, out);

    cudaEventDestroy(evFork);
    cudaEventDestroy(evJoin);
    cudaStreamDestroy(s2);
}